// round 2
// baseline (speedup 1.0000x reference)
#include <cuda_runtime.h>
#include <cuda_bf16.h>
#include <cstdint>

#define Bc 2
#define Hc 16
#define Sc 2048
#define Dc 128
#define TOT (Bc*Hc*Sc*Dc)

#define BM 128
#define BN 128
#define LDT 136   // padded smem leading dim (bf16 elems): 272B rows -> conflict-free ldmatrix

// Scratch (allocation-free rule: __device__ globals)
__device__ __nv_bfloat16 g_Qb[TOT];
__device__ __nv_bfloat16 g_Kb[TOT];
__device__ float g_pos[Bc*Sc];

// ---------------------------------------------------------------------------
// Prepass: q *= head_scale/sqrt(D) -> bf16 ; k -> bf16 ; gather positions
// ---------------------------------------------------------------------------
__global__ void prep_kernel(const float* __restrict__ q, const float* __restrict__ k,
                            const float* __restrict__ head_scales,
                            const float* __restrict__ positions,
                            const int* __restrict__ tok) {
    int tid = blockIdx.x * blockDim.x + threadIdx.x;
    int base = tid * 8;
    if (base < TOT) {
        // elements per (b,h) slice = S*D = 2^18 ; all 8 elems share h
        int h = (base >> 18) & (Hc - 1);
        float sc = head_scales[h] * 0.08838834764831845f; // 1/sqrt(128)

        float4 q0 = ((const float4*)q)[tid * 2];
        float4 q1 = ((const float4*)q)[tid * 2 + 1];
        __nv_bfloat162 qp[4];
        qp[0] = __floats2bfloat162_rn(q0.x * sc, q0.y * sc);
        qp[1] = __floats2bfloat162_rn(q0.z * sc, q0.w * sc);
        qp[2] = __floats2bfloat162_rn(q1.x * sc, q1.y * sc);
        qp[3] = __floats2bfloat162_rn(q1.z * sc, q1.w * sc);
        *(uint4*)(g_Qb + base) = *(uint4*)qp;

        float4 k0 = ((const float4*)k)[tid * 2];
        float4 k1 = ((const float4*)k)[tid * 2 + 1];
        __nv_bfloat162 kp[4];
        kp[0] = __floats2bfloat162_rn(k0.x, k0.y);
        kp[1] = __floats2bfloat162_rn(k0.z, k0.w);
        kp[2] = __floats2bfloat162_rn(k1.x, k1.y);
        kp[3] = __floats2bfloat162_rn(k1.z, k1.w);
        *(uint4*)(g_Kb + base) = *(uint4*)kp;
    }
    if (tid < Bc * Sc) {
        g_pos[tid] = positions[tok[tid]];
    }
}

// ---------------------------------------------------------------------------
// Main kernel: per (b,h), C[128x128 tile] = Qb * Kb^T, epilogue ALiBi bias
// 256 threads = 8 warps (4 m-warps x 2 n-warps), warp tile 32x64, K=128 full.
// ---------------------------------------------------------------------------
__device__ __forceinline__ void ldsm_x4(uint32_t addr, uint32_t* r) {
    asm volatile("ldmatrix.sync.aligned.m8n8.x4.shared.b16 {%0,%1,%2,%3}, [%4];\n"
                 : "=r"(r[0]), "=r"(r[1]), "=r"(r[2]), "=r"(r[3]) : "r"(addr));
}

__device__ __forceinline__ void mma_16816(float* c, const uint32_t* a, uint32_t b0, uint32_t b1) {
    asm volatile("mma.sync.aligned.m16n8k16.row.col.f32.bf16.bf16.f32 "
                 "{%0,%1,%2,%3}, {%4,%5,%6,%7}, {%8,%9}, {%0,%1,%2,%3};\n"
                 : "+f"(c[0]), "+f"(c[1]), "+f"(c[2]), "+f"(c[3])
                 : "r"(a[0]), "r"(a[1]), "r"(a[2]), "r"(a[3]), "r"(b0), "r"(b1));
}

__global__ void __launch_bounds__(256, 2)
score_kernel(float* __restrict__ out, const float* __restrict__ slopes) {
    extern __shared__ char smem_raw[];
    __nv_bfloat16* qs = (__nv_bfloat16*)smem_raw;
    __nv_bfloat16* ks = qs + BM * LDT;
    float* rowPos = (float*)(ks + BN * LDT);
    float* colPos = rowPos + BM;

    const int nT = blockIdx.x;
    const int mT = blockIdx.y;
    const int z  = blockIdx.z;           // b*H + h
    const int b  = z >> 4;
    const int h  = z & 15;
    const int t  = threadIdx.x;

    const __nv_bfloat16* Qg = g_Qb + (size_t)z * Sc * Dc + (size_t)mT * BM * Dc;
    const __nv_bfloat16* Kg = g_Kb + (size_t)z * Sc * Dc + (size_t)nT * BN * Dc;

    // Stage tiles (bf16, 128x128 each) into padded smem; uint4 = 8 bf16
    #pragma unroll
    for (int i = t; i < BM * 16; i += 256) {
        int r = i >> 4, c = i & 15;
        *(uint4*)(qs + r * LDT + c * 8) = ((const uint4*)(Qg + r * Dc))[c];
        *(uint4*)(ks + r * LDT + c * 8) = ((const uint4*)(Kg + r * Dc))[c];
    }
    if (t < BM)       rowPos[t]       = g_pos[b * Sc + mT * BM + t];
    else              colPos[t - BM]  = g_pos[b * Sc + nT * BN + (t - BM)];
    __syncthreads();

    const int lane = t & 31, wid = t >> 5;
    const int wm = (wid & 3) * 32;   // warp m offset (0,32,64,96)
    const int wn = (wid >> 2) * 64;  // warp n offset (0,64)

    float acc[2][8][4];
    #pragma unroll
    for (int im = 0; im < 2; im++)
        #pragma unroll
        for (int in = 0; in < 8; in++)
            #pragma unroll
            for (int r = 0; r < 4; r++) acc[im][in][r] = 0.0f;

    const uint32_t qbase = (uint32_t)__cvta_generic_to_shared(qs);
    const uint32_t kbase = (uint32_t)__cvta_generic_to_shared(ks);
    const int lr = lane & 15;            // row within 16-row ldmatrix group
    const int lc = (lane >> 4) * 8;      // col half select

    #pragma unroll
    for (int kk = 0; kk < 8; kk++) {
        const int k0 = kk * 16;
        uint32_t a[2][4];
        #pragma unroll
        for (int im = 0; im < 2; im++)
            ldsm_x4(qbase + (uint32_t)(((wm + im * 16 + lr) * LDT + k0 + lc) * 2), a[im]);
        uint32_t br[4][4];
        #pragma unroll
        for (int in2 = 0; in2 < 4; in2++)
            ldsm_x4(kbase + (uint32_t)(((wn + in2 * 16 + lr) * LDT + k0 + lc) * 2), br[in2]);
        #pragma unroll
        for (int im = 0; im < 2; im++)
            #pragma unroll
            for (int in = 0; in < 8; in++) {
                int in2 = in >> 1, sub = in & 1;
                mma_16816(acc[im][in], a[im], br[in2][sub], br[in2][sub + 2]);
            }
    }

    // Epilogue: out = score - slope*(pos_q - pos_k)
    const float slope = slopes[h];
    const int qr0 = lane >> 2;          // 0..7
    const int cc0 = (lane & 3) * 2;     // 0,2,4,6
    const size_t outBase = (size_t)z * Sc * Sc;

    #pragma unroll
    for (int im = 0; im < 2; im++) {
        const int rA = wm + im * 16 + qr0;
        const int rB = rA + 8;
        const float prA = rowPos[rA] * slope;
        const float prB = rowPos[rB] * slope;
        const size_t gRowA = (size_t)(mT * BM + rA);
        #pragma unroll
        for (int in = 0; in < 8; in++) {
            const int cl = wn + in * 8 + cc0;
            const float pc0 = colPos[cl] * slope;
            const float pc1 = colPos[cl + 1] * slope;
            const size_t gcol = (size_t)(nT * BN + cl);
            float2 v0, v1;
            v0.x = acc[im][in][0] - prA + pc0;
            v0.y = acc[im][in][1] - prA + pc1;
            v1.x = acc[im][in][2] - prB + pc0;
            v1.y = acc[im][in][3] - prB + pc1;
            *(float2*)(out + outBase + gRowA * Sc + gcol)       = v0;
            *(float2*)(out + outBase + (gRowA + 8) * Sc + gcol) = v1;
        }
    }
}

// ---------------------------------------------------------------------------
extern "C" void kernel_launch(void* const* d_in, const int* in_sizes, int n_in,
                              void* d_out, int out_size) {
    const float* q         = (const float*)d_in[0];
    const float* k         = (const float*)d_in[1];
    const float* hs        = (const float*)d_in[2];
    const float* slopes    = (const float*)d_in[3];
    const float* positions = (const float*)d_in[4];
    const int*   tok       = (const int*)d_in[5];
    float* out = (float*)d_out;

    // Prepass: 8 elems/thread over TOT
    prep_kernel<<<TOT / 8 / 256, 256>>>(q, k, hs, positions, tok);

    const int smem_bytes = 2 * BM * LDT * 2 /*bf16 tiles*/ + 2 * BM * 4 /*pos*/;
    cudaFuncSetAttribute(score_kernel, cudaFuncAttributeMaxDynamicSharedMemorySize, smem_bytes);
    dim3 grid(Sc / BN, Sc / BM, Bc * Hc);
    score_kernel<<<grid, 256, smem_bytes>>>(out, slopes);
}

// round 4
// speedup vs baseline: 1.1149x; 1.1149x over previous
#include <cuda_runtime.h>
#include <cuda_bf16.h>
#include <cstdint>

#define Bc 2
#define Hc 16
#define Sc 2048
#define Dc 128
#define TOT (Bc*Hc*Sc*Dc)

#define BM 128
#define BN 128
#define NT 4            // nT tiles per CTA (persistent, K double-buffered)
#define LDT 136         // padded smem leading dim (bf16): 272B rows
#define TILE_B (BM*LDT*2)   // 34816 bytes per 128x128 bf16 tile

// Scratch (allocation-free rule: __device__ globals)
__device__ __nv_bfloat16 g_Qb[TOT];
__device__ __nv_bfloat16 g_Kb[TOT];
__device__ float g_pos[Bc*Sc];

// ---------------------------------------------------------------------------
// Prepass: q *= head_scale/sqrt(D) -> bf16 ; k -> bf16 ; gather positions
// ---------------------------------------------------------------------------
__global__ void prep_kernel(const float* __restrict__ q, const float* __restrict__ k,
                            const float* __restrict__ head_scales,
                            const float* __restrict__ positions,
                            const int* __restrict__ tok) {
    int tid = blockIdx.x * blockDim.x + threadIdx.x;
    int base = tid * 8;
    if (base < TOT) {
        int h = (base >> 18) & (Hc - 1);   // S*D = 2^18 elems per (b,h)
        float sc = head_scales[h] * 0.08838834764831845f; // 1/sqrt(128)

        float4 q0 = ((const float4*)q)[tid * 2];
        float4 q1 = ((const float4*)q)[tid * 2 + 1];
        __nv_bfloat162 qp[4];
        qp[0] = __floats2bfloat162_rn(q0.x * sc, q0.y * sc);
        qp[1] = __floats2bfloat162_rn(q0.z * sc, q0.w * sc);
        qp[2] = __floats2bfloat162_rn(q1.x * sc, q1.y * sc);
        qp[3] = __floats2bfloat162_rn(q1.z * sc, q1.w * sc);
        *(uint4*)(g_Qb + base) = *(uint4*)qp;

        float4 k0 = ((const float4*)k)[tid * 2];
        float4 k1 = ((const float4*)k)[tid * 2 + 1];
        __nv_bfloat162 kp[4];
        kp[0] = __floats2bfloat162_rn(k0.x, k0.y);
        kp[1] = __floats2bfloat162_rn(k0.z, k0.w);
        kp[2] = __floats2bfloat162_rn(k1.x, k1.y);
        kp[3] = __floats2bfloat162_rn(k1.z, k1.w);
        *(uint4*)(g_Kb + base) = *(uint4*)kp;
    }
    if (tid < Bc * Sc) {
        g_pos[tid] = positions[tok[tid]];
    }
}

// ---------------------------------------------------------------------------
// HMMA helpers
// ---------------------------------------------------------------------------
__device__ __forceinline__ void ldsm_x4(uint32_t addr, uint32_t* r) {
    asm volatile("ldmatrix.sync.aligned.m8n8.x4.shared.b16 {%0,%1,%2,%3}, [%4];\n"
                 : "=r"(r[0]), "=r"(r[1]), "=r"(r[2]), "=r"(r[3]) : "r"(addr));
}
__device__ __forceinline__ void mma_16816(float* c, const uint32_t* a, uint32_t b0, uint32_t b1) {
    asm volatile("mma.sync.aligned.m16n8k16.row.col.f32.bf16.bf16.f32 "
                 "{%0,%1,%2,%3}, {%4,%5,%6,%7}, {%8,%9}, {%0,%1,%2,%3};\n"
                 : "+f"(c[0]), "+f"(c[1]), "+f"(c[2]), "+f"(c[3])
                 : "r"(a[0]), "r"(a[1]), "r"(a[2]), "r"(a[3]), "r"(b0), "r"(b1));
}
__device__ __forceinline__ void cp16(uint32_t dst, const void* src) {
    asm volatile("cp.async.cg.shared.global [%0], [%1], 16;" :: "r"(dst), "l"(src));
}
#define CP_COMMIT() asm volatile("cp.async.commit_group;" ::: "memory")
#define CP_WAIT0()  asm volatile("cp.async.wait_group 0;" ::: "memory")

// ---------------------------------------------------------------------------
// Score kernel: per CTA, fixed (z, mT); loops over NT consecutive nT tiles.
// Q staged once; K double-buffered with cp.async; 8 warps, warp tile 32x64.
// ---------------------------------------------------------------------------
__global__ void __launch_bounds__(256, 2)
score_kernel(float* __restrict__ out, const float* __restrict__ slopes) {
    extern __shared__ char smem_raw[];
    __nv_bfloat16* qs  = (__nv_bfloat16*)smem_raw;                 // TILE_B
    __nv_bfloat16* ks0 = qs + BM * LDT;                            // 2x TILE_B
    float* rowPos = (float*)(smem_raw + 3 * TILE_B);               // 128 f
    float* colPosB = rowPos + BM;                                  // 2 x 128 f

    const int nT0 = blockIdx.x * NT;
    const int mT  = blockIdx.y;
    const int z   = blockIdx.z;           // b*H + h
    const int b   = z >> 4;
    const int h   = z & 15;
    const int t   = threadIdx.x;

    const uint32_t sq = (uint32_t)__cvta_generic_to_shared(qs);
    const uint32_t sk = (uint32_t)__cvta_generic_to_shared(ks0);

    const float slope = __ldg(slopes + h);
    const size_t zoff = (size_t)z * Sc * Dc;
    const __nv_bfloat16* Qg = g_Qb + zoff + (size_t)mT * BM * Dc;

    // Stage Q (once) + K tile 0, async
    #pragma unroll
    for (int i = t; i < BM * 16; i += 256) {
        int r = i >> 4, c = i & 15;
        cp16(sq + (uint32_t)(r * (LDT*2) + c * 16), Qg + r * Dc + c * 8);
    }
    {
        const __nv_bfloat16* Kg = g_Kb + zoff + (size_t)nT0 * BN * Dc;
        #pragma unroll
        for (int i = t; i < BN * 16; i += 256) {
            int r = i >> 4, c = i & 15;
            cp16(sk + (uint32_t)(r * (LDT*2) + c * 16), Kg + r * Dc + c * 8);
        }
    }
    CP_COMMIT();

    if (t < BM)       rowPos[t]        = g_pos[b * Sc + mT * BM + t] * slope;
    else              colPosB[t - BM]  = g_pos[b * Sc + nT0 * BN + (t - BM)] * slope; // buf 0

    CP_WAIT0();
    __syncthreads();

    const int lane = t & 31, wid = t >> 5;
    const int wm = (wid & 3) * 32;   // warp m offset
    const int wn = (wid >> 2) * 64;  // warp n offset
    const int lr = lane & 15;
    const int lc = (lane >> 4) * 8;
    const int qr0 = lane >> 2;
    const int cc0 = (lane & 3) * 2;

    const size_t outBase = (size_t)z * Sc * Sc;

    for (int it = 0; it < NT; it++) {
        const int cur = it & 1, nxt = cur ^ 1;
        const uint32_t kb = sk + (uint32_t)cur * TILE_B;

        // Prefetch next K tile + next colPos into the other buffer
        if (it < NT - 1) {
            const __nv_bfloat16* Kg = g_Kb + zoff + (size_t)(nT0 + it + 1) * BN * Dc;
            #pragma unroll
            for (int i = t; i < BN * 16; i += 256) {
                int r = i >> 4, c = i & 15;
                cp16(sk + (uint32_t)(nxt * TILE_B + r * (LDT*2) + c * 16), Kg + r * Dc + c * 8);
            }
            CP_COMMIT();
            if (t < BN)
                colPosB[nxt * BN + t] = g_pos[b * Sc + (nT0 + it + 1) * BN + t] * slope;
        }

        // ---- compute 128x128 tile ----
        float acc[2][8][4];
        #pragma unroll
        for (int im = 0; im < 2; im++)
            #pragma unroll
            for (int in = 0; in < 8; in++)
                #pragma unroll
                for (int r = 0; r < 4; r++) acc[im][in][r] = 0.0f;

        #pragma unroll
        for (int kk = 0; kk < 8; kk++) {
            const int k0 = kk * 16;
            uint32_t a[2][4];
            #pragma unroll
            for (int im = 0; im < 2; im++)
                ldsm_x4(sq + (uint32_t)(((wm + im * 16 + lr) * LDT + k0 + lc) * 2), a[im]);
            uint32_t br[4][4];
            #pragma unroll
            for (int in2 = 0; in2 < 4; in2++)
                ldsm_x4(kb + (uint32_t)(((wn + in2 * 16 + lr) * LDT + k0 + lc) * 2), br[in2]);
            #pragma unroll
            for (int im = 0; im < 2; im++)
                #pragma unroll
                for (int in = 0; in < 8; in++) {
                    int in2 = in >> 1, sub = in & 1;
                    mma_16816(acc[im][in], a[im], br[in2][sub], br[in2][sub + 2]);
                }
        }

        // ---- epilogue: out = score - slope*pos_q + slope*pos_k ----
        const float* cp = colPosB + cur * BN;
        #pragma unroll
        for (int im = 0; im < 2; im++) {
            const int rA = wm + im * 16 + qr0;
            const float prA = rowPos[rA];
            const float prB = rowPos[rA + 8];
            const size_t gRowA = (size_t)(mT * BM + rA);
            float* oA = out + outBase + gRowA * Sc + (size_t)(nT0 + it) * BN;
            float* oB = oA + 8 * Sc;
            #pragma unroll
            for (int in = 0; in < 8; in++) {
                const int cl = wn + in * 8 + cc0;
                const float pc0 = cp[cl];
                const float pc1 = cp[cl + 1];
                float2 v0, v1;
                v0.x = acc[im][in][0] - prA + pc0;
                v0.y = acc[im][in][1] - prA + pc1;
                v1.x = acc[im][in][2] - prB + pc0;
                v1.y = acc[im][in][3] - prB + pc1;
                *(float2*)(oA + cl) = v0;
                *(float2*)(oB + cl) = v1;
            }
        }

        if (it < NT - 1) {
            CP_WAIT0();
            __syncthreads();
        }
    }
}

// ---------------------------------------------------------------------------
extern "C" void kernel_launch(void* const* d_in, const int* in_sizes, int n_in,
                              void* d_out, int out_size) {
    const float* q         = (const float*)d_in[0];
    const float* k         = (const float*)d_in[1];
    const float* hs        = (const float*)d_in[2];
    const float* slopes    = (const float*)d_in[3];
    const float* positions = (const float*)d_in[4];
    const int*   tok       = (const int*)d_in[5];
    float* out = (float*)d_out;

    prep_kernel<<<TOT / 8 / 256, 256>>>(q, k, hs, positions, tok);

    const int smem_bytes = 3 * TILE_B + (BM + 2 * BN) * 4;
    cudaFuncSetAttribute(score_kernel, cudaFuncAttributeMaxDynamicSharedMemorySize, smem_bytes);
    dim3 grid(Sc / BN / NT, Sc / BM, Bc * Hc);
    score_kernel<<<grid, 256, smem_bytes>>>(out, slopes);
}

// round 5
// speedup vs baseline: 1.1284x; 1.0121x over previous
#include <cuda_runtime.h>
#include <cuda_bf16.h>
#include <cstdint>

#define Bc 2
#define Hc 16
#define Sc 2048
#define Dc 128
#define TOT (Bc*Hc*Sc*Dc)

#define BM 128
#define BN 128
#define NT 4            // nT tiles per CTA (persistent, K double-buffered)
#define LDT 136         // padded smem leading dim (bf16): 272B rows
#define TILE_B (BM*LDT*2)   // 34816 bytes per 128x128 bf16 tile

// Scratch (allocation-free rule: __device__ globals)
__device__ __nv_bfloat16 g_Qb[TOT];
__device__ __nv_bfloat16 g_Kb[TOT];
__device__ float g_pos[Bc*Sc];

// ---------------------------------------------------------------------------
// Prepass: q *= head_scale/sqrt(D) -> bf16 ; k -> bf16 ; gather positions
// ---------------------------------------------------------------------------
__global__ void prep_kernel(const float* __restrict__ q, const float* __restrict__ k,
                            const float* __restrict__ head_scales,
                            const float* __restrict__ positions,
                            const int* __restrict__ tok) {
    int tid = blockIdx.x * blockDim.x + threadIdx.x;
    int base = tid * 8;
    if (base < TOT) {
        int h = (base >> 18) & (Hc - 1);   // S*D = 2^18 elems per (b,h)
        float sc = head_scales[h] * 0.08838834764831845f; // 1/sqrt(128)

        float4 q0 = ((const float4*)q)[tid * 2];
        float4 q1 = ((const float4*)q)[tid * 2 + 1];
        __nv_bfloat162 qp[4];
        qp[0] = __floats2bfloat162_rn(q0.x * sc, q0.y * sc);
        qp[1] = __floats2bfloat162_rn(q0.z * sc, q0.w * sc);
        qp[2] = __floats2bfloat162_rn(q1.x * sc, q1.y * sc);
        qp[3] = __floats2bfloat162_rn(q1.z * sc, q1.w * sc);
        *(uint4*)(g_Qb + base) = *(uint4*)qp;

        float4 k0 = ((const float4*)k)[tid * 2];
        float4 k1 = ((const float4*)k)[tid * 2 + 1];
        __nv_bfloat162 kp[4];
        kp[0] = __floats2bfloat162_rn(k0.x, k0.y);
        kp[1] = __floats2bfloat162_rn(k0.z, k0.w);
        kp[2] = __floats2bfloat162_rn(k1.x, k1.y);
        kp[3] = __floats2bfloat162_rn(k1.z, k1.w);
        *(uint4*)(g_Kb + base) = *(uint4*)kp;
    }
    if (tid < Bc * Sc) {
        g_pos[tid] = positions[tok[tid]];
    }
}

// ---------------------------------------------------------------------------
// HMMA helpers
// ---------------------------------------------------------------------------
__device__ __forceinline__ void ldsm_x4(uint32_t addr, uint32_t* r) {
    asm volatile("ldmatrix.sync.aligned.m8n8.x4.shared.b16 {%0,%1,%2,%3}, [%4];\n"
                 : "=r"(r[0]), "=r"(r[1]), "=r"(r[2]), "=r"(r[3]) : "r"(addr));
}
__device__ __forceinline__ void mma_16816(float* c, const uint32_t* a, uint32_t b0, uint32_t b1) {
    asm volatile("mma.sync.aligned.m16n8k16.row.col.f32.bf16.bf16.f32 "
                 "{%0,%1,%2,%3}, {%4,%5,%6,%7}, {%8,%9}, {%0,%1,%2,%3};\n"
                 : "+f"(c[0]), "+f"(c[1]), "+f"(c[2]), "+f"(c[3])
                 : "r"(a[0]), "r"(a[1]), "r"(a[2]), "r"(a[3]), "r"(b0), "r"(b1));
}
__device__ __forceinline__ void cp16(uint32_t dst, const void* src) {
    asm volatile("cp.async.cg.shared.global [%0], [%1], 16;" :: "r"(dst), "l"(src));
}
#define CP_COMMIT() asm volatile("cp.async.commit_group;" ::: "memory")
#define CP_WAIT0()  asm volatile("cp.async.wait_group 0;" ::: "memory")

// ---------------------------------------------------------------------------
// Score kernel: per CTA, fixed (z, mT); loops over NT consecutive nT tiles.
// Q staged once; K double-buffered via cp.async; fragments double-buffered in
// registers so LDSM latency hides under MMA issue. 8 warps, warp tile 32x64.
// ---------------------------------------------------------------------------
__global__ void __launch_bounds__(256, 2)
score_kernel(float* __restrict__ out, const float* __restrict__ slopes) {
    extern __shared__ char smem_raw[];
    __nv_bfloat16* qs  = (__nv_bfloat16*)smem_raw;                 // TILE_B
    __nv_bfloat16* ks0 = qs + BM * LDT;                            // 2x TILE_B
    float* rowPos = (float*)(smem_raw + 3 * TILE_B);               // 128 f
    float* colPosB = rowPos + BM;                                  // 2 x 128 f

    const int nT0 = blockIdx.x * NT;
    const int mT  = blockIdx.y;
    const int z   = blockIdx.z;           // b*H + h
    const int b   = z >> 4;
    const int h   = z & 15;
    const int t   = threadIdx.x;

    const uint32_t sq = (uint32_t)__cvta_generic_to_shared(qs);
    const uint32_t sk = (uint32_t)__cvta_generic_to_shared(ks0);

    const float slope = __ldg(slopes + h);
    const size_t zoff = (size_t)z * Sc * Dc;
    const __nv_bfloat16* Qg = g_Qb + zoff + (size_t)mT * BM * Dc;

    // Stage Q (once) + K tile 0, async
    #pragma unroll
    for (int i = t; i < BM * 16; i += 256) {
        int r = i >> 4, c = i & 15;
        cp16(sq + (uint32_t)(r * (LDT*2) + c * 16), Qg + r * Dc + c * 8);
    }
    {
        const __nv_bfloat16* Kg = g_Kb + zoff + (size_t)nT0 * BN * Dc;
        #pragma unroll
        for (int i = t; i < BN * 16; i += 256) {
            int r = i >> 4, c = i & 15;
            cp16(sk + (uint32_t)(r * (LDT*2) + c * 16), Kg + r * Dc + c * 8);
        }
    }
    CP_COMMIT();

    if (t < BM)       rowPos[t]        = g_pos[b * Sc + mT * BM + t] * slope;
    else              colPosB[t - BM]  = g_pos[b * Sc + nT0 * BN + (t - BM)] * slope; // buf 0

    CP_WAIT0();
    __syncthreads();

    const int lane = t & 31, wid = t >> 5;
    const int wm = (wid & 3) * 32;   // warp m offset
    const int wn = (wid >> 2) * 64;  // warp n offset
    const int lr = lane & 15;
    const int lc = (lane >> 4) * 8;
    const int qr0 = lane >> 2;
    const int cc0 = (lane & 3) * 2;

    // Precomputed ldsm base addresses (byte offsets within tile buffers)
    uint32_t aAddr[2], bOff[4];
    #pragma unroll
    for (int im = 0; im < 2; im++)
        aAddr[im] = sq + (uint32_t)(((wm + im * 16 + lr) * LDT + lc) * 2);
    #pragma unroll
    for (int in2 = 0; in2 < 4; in2++)
        bOff[in2] = (uint32_t)(((wn + in2 * 16 + lr) * LDT + lc) * 2);

    const size_t outBase = (size_t)z * Sc * Sc;

    for (int it = 0; it < NT; it++) {
        const int cur = it & 1, nxt = cur ^ 1;
        const uint32_t kb = sk + (uint32_t)cur * TILE_B;

        // Prefetch next K tile + next colPos into the other buffer
        if (it < NT - 1) {
            const __nv_bfloat16* Kg = g_Kb + zoff + (size_t)(nT0 + it + 1) * BN * Dc;
            #pragma unroll
            for (int i = t; i < BN * 16; i += 256) {
                int r = i >> 4, c = i & 15;
                cp16(sk + (uint32_t)(nxt * TILE_B + r * (LDT*2) + c * 16), Kg + r * Dc + c * 8);
            }
            CP_COMMIT();
            if (t < BN)
                colPosB[nxt * BN + t] = g_pos[b * Sc + (nT0 + it + 1) * BN + t] * slope;
        }

        // ---- compute 128x128 tile, register-double-buffered fragments ----
        float acc[2][8][4];
        #pragma unroll
        for (int im = 0; im < 2; im++)
            #pragma unroll
            for (int in = 0; in < 8; in++)
                #pragma unroll
                for (int r = 0; r < 4; r++) acc[im][in][r] = 0.0f;

        uint32_t a[2][2][4];   // [buf][im][reg]
        uint32_t brf[2][4][4]; // [buf][in2][reg]

        // Preload k-step 0
        #pragma unroll
        for (int im = 0; im < 2; im++) ldsm_x4(aAddr[im], a[0][im]);
        #pragma unroll
        for (int in2 = 0; in2 < 4; in2++) ldsm_x4(kb + bOff[in2], brf[0][in2]);

        #pragma unroll
        for (int kk = 0; kk < 8; kk++) {
            const int fc = kk & 1, fn = fc ^ 1;
            // Issue next k-step LDSMs first (latency hides under MMAs below)
            if (kk < 7) {
                const uint32_t ko = (uint32_t)((kk + 1) * 32); // 16 bf16 = 32B
                #pragma unroll
                for (int im = 0; im < 2; im++) ldsm_x4(aAddr[im] + ko, a[fn][im]);
                #pragma unroll
                for (int in2 = 0; in2 < 4; in2++) ldsm_x4(kb + bOff[in2] + ko, brf[fn][in2]);
            }
            #pragma unroll
            for (int im = 0; im < 2; im++)
                #pragma unroll
                for (int in = 0; in < 8; in++) {
                    int in2 = in >> 1, sub = in & 1;
                    mma_16816(acc[im][in], a[fc][im], brf[fc][in2][sub], brf[fc][in2][sub + 2]);
                }
        }

        // ---- epilogue: out = score - slope*pos_q + slope*pos_k ----
        const float* cp = colPosB + cur * BN;
        #pragma unroll
        for (int im = 0; im < 2; im++) {
            const int rA = wm + im * 16 + qr0;
            const float prA = rowPos[rA];
            const float prB = rowPos[rA + 8];
            const size_t gRowA = (size_t)(mT * BM + rA);
            float* oA = out + outBase + gRowA * Sc + (size_t)(nT0 + it) * BN;
            float* oB = oA + 8 * Sc;
            #pragma unroll
            for (int in = 0; in < 8; in++) {
                const int cl = wn + in * 8 + cc0;
                const float pc0 = cp[cl];
                const float pc1 = cp[cl + 1];
                float2 v0, v1;
                v0.x = acc[im][in][0] - prA + pc0;
                v0.y = acc[im][in][1] - prA + pc1;
                v1.x = acc[im][in][2] - prB + pc0;
                v1.y = acc[im][in][3] - prB + pc1;
                *(float2*)(oA + cl) = v0;
                *(float2*)(oB + cl) = v1;
            }
        }

        if (it < NT - 1) {
            CP_WAIT0();
            __syncthreads();
        }
    }
}

// ---------------------------------------------------------------------------
extern "C" void kernel_launch(void* const* d_in, const int* in_sizes, int n_in,
                              void* d_out, int out_size) {
    const float* q         = (const float*)d_in[0];
    const float* k         = (const float*)d_in[1];
    const float* hs        = (const float*)d_in[2];
    const float* slopes    = (const float*)d_in[3];
    const float* positions = (const float*)d_in[4];
    const int*   tok       = (const int*)d_in[5];
    float* out = (float*)d_out;

    prep_kernel<<<TOT / 8 / 256, 256>>>(q, k, hs, positions, tok);

    const int smem_bytes = 3 * TILE_B + (BM + 2 * BN) * 4;
    cudaFuncSetAttribute(score_kernel, cudaFuncAttributeMaxDynamicSharedMemorySize, smem_bytes);
    dim3 grid(Sc / BN / NT, Sc / BM, Bc * Hc);
    score_kernel<<<grid, 256, smem_bytes>>>(out, slopes);
}